// round 2
// baseline (speedup 1.0000x reference)
#include <cuda_runtime.h>

#define NROWS 8192
#define CDIM  512
#define DK    64

// Scratch (static __device__ globals — allocation-free per harness rules)
__device__ float g_Q1[NROWS * DK];
__device__ float g_K1[NROWS * DK];
__device__ float g_Q2[NROWS * DK];
__device__ float g_K2[NROWS * DK];
__device__ float g_V1[NROWS * CDIM];
__device__ float g_V2[NROWS * CDIM];

// ---------------------------------------------------------------------------
// Projection GEMM: OUT[N][OC] = X[N][512] @ W[512][OC], OC in {64, 512}
// 64x64 output tile, 256 threads, 4x4 per thread, K-chunk 16.
// ---------------------------------------------------------------------------
__global__ __launch_bounds__(256)
void proj_kernel(const float* __restrict__ X, const float* __restrict__ W,
                 float* __restrict__ OUT, int OC) {
    __shared__ float Xs[64][17];
    __shared__ float Ws[16][64];
    int tid  = threadIdx.x;
    int row0 = blockIdx.x * 64;
    int col0 = blockIdx.y * 64;

    int lr = tid >> 2, lc = (tid & 3) * 4;    // X loader
    int wr = tid >> 4, wc = (tid & 15) * 4;   // W loader
    int ty = tid >> 4, tx = tid & 15;         // compute mapping

    float acc[4][4];
    #pragma unroll
    for (int i = 0; i < 4; i++)
        #pragma unroll
        for (int j = 0; j < 4; j++) acc[i][j] = 0.f;

    for (int k0 = 0; k0 < CDIM; k0 += 16) {
        __syncthreads();
        float4 xv = *(const float4*)(X + (size_t)(row0 + lr) * CDIM + k0 + lc);
        Xs[lr][lc + 0] = xv.x; Xs[lr][lc + 1] = xv.y;
        Xs[lr][lc + 2] = xv.z; Xs[lr][lc + 3] = xv.w;
        *(float4*)(&Ws[wr][wc]) =
            *(const float4*)(W + (size_t)(k0 + wr) * OC + col0 + wc);
        __syncthreads();
        #pragma unroll
        for (int kk = 0; kk < 16; kk++) {
            float a[4], b[4];
            #pragma unroll
            for (int i = 0; i < 4; i++) a[i] = Xs[ty * 4 + i][kk];
            #pragma unroll
            for (int j = 0; j < 4; j++) b[j] = Ws[kk][tx * 4 + j];
            #pragma unroll
            for (int i = 0; i < 4; i++)
                #pragma unroll
                for (int j = 0; j < 4; j++)
                    acc[i][j] = fmaf(a[i], b[j], acc[i][j]);
        }
    }
    #pragma unroll
    for (int i = 0; i < 4; i++) {
        float4 o = make_float4(acc[i][0], acc[i][1], acc[i][2], acc[i][3]);
        *(float4*)(OUT + (size_t)(row0 + ty * 4 + i) * OC + col0 + tx * 4) = o;
    }
}

// ---------------------------------------------------------------------------
// Fused attention: O = softmax(Q @ K^T) @ V + R   (no max-subtraction;
// logits are bounded ~|61| for this data so exp stays well inside fp32).
// CTA = 32 query rows x 512 cols. Key tiles of 32.
// blockIdx.y selects direction.
// ---------------------------------------------------------------------------
__global__ __launch_bounds__(256, 2)
void attn_kernel(const float* __restrict__ im1, const float* __restrict__ im2,
                 float* __restrict__ out) {
    const float *Q, *K, *V, *R;
    float* O;
    if (blockIdx.y == 0) { Q = g_Q2; K = g_K1; V = g_V1; R = im1; O = out; }
    else                 { Q = g_Q1; K = g_K2; V = g_V2; R = im2;
                           O = out + (size_t)NROWS * CDIM; }

    extern __shared__ float sm[];
    float* qs  = sm;                 // [32][68]
    float* ks  = qs + 32 * 68;       // [32][68]
    float* vs  = ks + 32 * 68;       // [32][512]
    float* ws  = vs + 32 * 512;      // [32][33]
    float* red = ws + 32 * 33;       // [256]
    float* den = red + 256;          // [32]

    int tid = threadIdx.x;
    int q0  = blockIdx.x * 32;

    // Load Q tile (32x64) into padded smem
    #pragma unroll
    for (int t = 0; t < 2; t++) {
        int e = tid + t * 256;
        int r = e >> 4, c = (e & 15) * 4;
        float4 v4 = *(const float4*)(Q + (size_t)(q0 + r) * DK + c);
        qs[r * 68 + c + 0] = v4.x; qs[r * 68 + c + 1] = v4.y;
        qs[r * 68 + c + 2] = v4.z; qs[r * 68 + c + 3] = v4.w;
    }

    float acc[4][16];
    #pragma unroll
    for (int i = 0; i < 4; i++)
        #pragma unroll
        for (int j = 0; j < 16; j++) acc[i][j] = 0.f;
    float dsum = 0.f;

    int li = tid >> 3;          // logit row  (0..31)
    int lj = tid & 7;           // logit col base lane (consecutive j, no conflicts)
    int tx = tid & 31;          // gemm col lane
    int ty = tid >> 5;          // gemm row base (0..7)

    for (int kt = 0; kt < NROWS / 32; kt++) {
        int k0 = kt * 32;
        __syncthreads();
        // Load K tile (32x64)
        #pragma unroll
        for (int t = 0; t < 2; t++) {
            int e = tid + t * 256;
            int r = e >> 4, c = (e & 15) * 4;
            float4 v4 = *(const float4*)(K + (size_t)(k0 + r) * DK + c);
            ks[r * 68 + c + 0] = v4.x; ks[r * 68 + c + 1] = v4.y;
            ks[r * 68 + c + 2] = v4.z; ks[r * 68 + c + 3] = v4.w;
        }
        // Load V tile (32x512)
        #pragma unroll
        for (int t = 0; t < 16; t++) {
            int e = tid + t * 256;
            int r = e >> 7, c = (e & 127) * 4;
            *(float4*)(vs + r * 512 + c) =
                *(const float4*)(V + (size_t)(k0 + r) * CDIM + c);
        }
        __syncthreads();

        // Logits + exp: each thread: row li, cols lj, lj+8, lj+16, lj+24
        #pragma unroll
        for (int jj = 0; jj < 4; jj++) {
            int j = lj + jj * 8;
            float4 s4 = make_float4(0.f, 0.f, 0.f, 0.f);
            #pragma unroll
            for (int d = 0; d < 16; d++) {
                float4 a = *(float4*)(qs + li * 68 + d * 4);
                float4 b = *(float4*)(ks + j  * 68 + d * 4);
                s4.x = fmaf(a.x, b.x, s4.x);
                s4.y = fmaf(a.y, b.y, s4.y);
                s4.z = fmaf(a.z, b.z, s4.z);
                s4.w = fmaf(a.w, b.w, s4.w);
            }
            float p = __expf((s4.x + s4.y) + (s4.z + s4.w));
            ws[li * 33 + j] = p;
            dsum += p;
        }
        __syncthreads();

        // O += P(32x32) @ V(32x512)
        #pragma unroll 4
        for (int kk = 0; kk < 32; kk++) {
            float w0 = ws[(ty     ) * 33 + kk];
            float w1 = ws[(ty +  8) * 33 + kk];
            float w2 = ws[(ty + 16) * 33 + kk];
            float w3 = ws[(ty + 24) * 33 + kk];
            #pragma unroll
            for (int i = 0; i < 4; i++) {
                float4 v4 = *(float4*)(vs + kk * 512 + i * 128 + tx * 4);
                acc[0][i*4+0] = fmaf(w0, v4.x, acc[0][i*4+0]);
                acc[0][i*4+1] = fmaf(w0, v4.y, acc[0][i*4+1]);
                acc[0][i*4+2] = fmaf(w0, v4.z, acc[0][i*4+2]);
                acc[0][i*4+3] = fmaf(w0, v4.w, acc[0][i*4+3]);
                acc[1][i*4+0] = fmaf(w1, v4.x, acc[1][i*4+0]);
                acc[1][i*4+1] = fmaf(w1, v4.y, acc[1][i*4+1]);
                acc[1][i*4+2] = fmaf(w1, v4.z, acc[1][i*4+2]);
                acc[1][i*4+3] = fmaf(w1, v4.w, acc[1][i*4+3]);
                acc[2][i*4+0] = fmaf(w2, v4.x, acc[2][i*4+0]);
                acc[2][i*4+1] = fmaf(w2, v4.y, acc[2][i*4+1]);
                acc[2][i*4+2] = fmaf(w2, v4.z, acc[2][i*4+2]);
                acc[2][i*4+3] = fmaf(w2, v4.w, acc[2][i*4+3]);
                acc[3][i*4+0] = fmaf(w3, v4.x, acc[3][i*4+0]);
                acc[3][i*4+1] = fmaf(w3, v4.y, acc[3][i*4+1]);
                acc[3][i*4+2] = fmaf(w3, v4.z, acc[3][i*4+2]);
                acc[3][i*4+3] = fmaf(w3, v4.w, acc[3][i*4+3]);
            }
        }
    }

    // Row-sum reduce (each thread holds partial for row li over its j-slice)
    red[tid] = dsum;
    __syncthreads();
    if (tid < 32) {
        float s = 0.f;
        #pragma unroll
        for (int t = 0; t < 8; t++) s += red[tid * 8 + t];
        den[tid] = 1.f / s;
    }
    __syncthreads();

    // Normalize + residual + store
    #pragma unroll
    for (int r = 0; r < 4; r++) {
        int rr  = ty + r * 8;
        int row = q0 + rr;
        float inv = den[rr];
        #pragma unroll
        for (int i = 0; i < 4; i++) {
            int col = i * 128 + tx * 4;
            float4 res = *(const float4*)(R + (size_t)row * CDIM + col);
            float4 o;
            o.x = fmaf(acc[r][i*4+0], inv, res.x);
            o.y = fmaf(acc[r][i*4+1], inv, res.y);
            o.z = fmaf(acc[r][i*4+2], inv, res.z);
            o.w = fmaf(acc[r][i*4+3], inv, res.w);
            *(float4*)(O + (size_t)row * CDIM + col) = o;
        }
    }
}

// ---------------------------------------------------------------------------
extern "C" void kernel_launch(void* const* d_in, const int* in_sizes, int n_in,
                              void* d_out, int out_size) {
    const float* im1 = (const float*)d_in[0];
    const float* im2 = (const float*)d_in[1];
    const float* Wq  = (const float*)d_in[2];
    const float* Wk  = (const float*)d_in[3];
    const float* Wv  = (const float*)d_in[4];
    float* out = (float*)d_out;

    float *Q1, *K1, *Q2, *K2, *V1, *V2;
    cudaGetSymbolAddress((void**)&Q1, g_Q1);
    cudaGetSymbolAddress((void**)&K1, g_K1);
    cudaGetSymbolAddress((void**)&Q2, g_Q2);
    cudaGetSymbolAddress((void**)&K2, g_K2);
    cudaGetSymbolAddress((void**)&V1, g_V1);
    cudaGetSymbolAddress((void**)&V2, g_V2);

    dim3 gq(NROWS / 64, 1);
    dim3 gv(NROWS / 64, CDIM / 64);
    proj_kernel<<<gq, 256>>>(im1, Wq, Q1, DK);
    proj_kernel<<<gq, 256>>>(im1, Wk, K1, DK);
    proj_kernel<<<gv, 256>>>(im1, Wv, V1, CDIM);
    proj_kernel<<<gq, 256>>>(im2, Wq, Q2, DK);
    proj_kernel<<<gq, 256>>>(im2, Wk, K2, DK);
    proj_kernel<<<gv, 256>>>(im2, Wv, V2, CDIM);

    int smem_bytes = (32 * 68 * 2 + 32 * 512 + 32 * 33 + 256 + 32) * (int)sizeof(float);
    cudaFuncSetAttribute(attn_kernel,
                         cudaFuncAttributeMaxDynamicSharedMemorySize, smem_bytes);
    attn_kernel<<<dim3(NROWS / 32, 2), 256, smem_bytes>>>(im1, im2, out);
}

// round 6
// speedup vs baseline: 3.1006x; 3.1006x over previous
#include <cuda_runtime.h>

#define NROWS 8192
#define CDIM  512
#define DK    64

// Scratch (static __device__ globals — allocation-free per harness rules)
__device__ float g_Q1[NROWS * DK];
__device__ float g_K1[NROWS * DK];
__device__ float g_Q2[NROWS * DK];
__device__ float g_K2[NROWS * DK];
__device__ float g_V1[NROWS * CDIM];
__device__ float g_V2[NROWS * CDIM];

// ---------------------------------------------------------------------------
// helpers: tf32 round-to-nearest, and m16n8k8 tf32 mma
// ---------------------------------------------------------------------------
__device__ __forceinline__ float tf32r(float x) {
    unsigned u;
    asm("cvt.rna.tf32.f32 %0, %1;" : "=r"(u) : "f"(x));
    return __uint_as_float(u);
}

__device__ __forceinline__ void mma8(float c[4], const float a[4], float b0, float b1) {
    asm volatile(
        "mma.sync.aligned.m16n8k8.row.col.f32.tf32.tf32.f32 "
        "{%0,%1,%2,%3},{%4,%5,%6,%7},{%8,%9},{%0,%1,%2,%3};"
        : "+f"(c[0]), "+f"(c[1]), "+f"(c[2]), "+f"(c[3])
        : "r"(__float_as_uint(a[0])), "r"(__float_as_uint(a[1])),
          "r"(__float_as_uint(a[2])), "r"(__float_as_uint(a[3])),
          "r"(__float_as_uint(b0)), "r"(__float_as_uint(b1)));
}

// ---------------------------------------------------------------------------
// FFMA projection GEMM (kept for Q/K: logits need full-fp32 Q,K)
// OUT[N][OC] = X[N][512] @ W[512][OC], OC = 64
// ---------------------------------------------------------------------------
__global__ __launch_bounds__(256)
void proj_kernel(const float* __restrict__ X, const float* __restrict__ W,
                 float* __restrict__ OUT, int OC) {
    __shared__ float Xs[64][17];
    __shared__ float Ws[16][64];
    int tid  = threadIdx.x;
    int row0 = blockIdx.x * 64;
    int col0 = blockIdx.y * 64;

    int lr = tid >> 2, lc = (tid & 3) * 4;
    int wr = tid >> 4, wc = (tid & 15) * 4;
    int ty = tid >> 4, tx = tid & 15;

    float acc[4][4];
    #pragma unroll
    for (int i = 0; i < 4; i++)
        #pragma unroll
        for (int j = 0; j < 4; j++) acc[i][j] = 0.f;

    for (int k0 = 0; k0 < CDIM; k0 += 16) {
        __syncthreads();
        float4 xv = *(const float4*)(X + (size_t)(row0 + lr) * CDIM + k0 + lc);
        Xs[lr][lc + 0] = xv.x; Xs[lr][lc + 1] = xv.y;
        Xs[lr][lc + 2] = xv.z; Xs[lr][lc + 3] = xv.w;
        *(float4*)(&Ws[wr][wc]) =
            *(const float4*)(W + (size_t)(k0 + wr) * OC + col0 + wc);
        __syncthreads();
        #pragma unroll
        for (int kk = 0; kk < 16; kk++) {
            float a[4], b[4];
            #pragma unroll
            for (int i = 0; i < 4; i++) a[i] = Xs[ty * 4 + i][kk];
            #pragma unroll
            for (int j = 0; j < 4; j++) b[j] = Ws[kk][tx * 4 + j];
            #pragma unroll
            for (int i = 0; i < 4; i++)
                #pragma unroll
                for (int j = 0; j < 4; j++)
                    acc[i][j] = fmaf(a[i], b[j], acc[i][j]);
        }
    }
    #pragma unroll
    for (int i = 0; i < 4; i++) {
        float4 o = make_float4(acc[i][0], acc[i][1], acc[i][2], acc[i][3]);
        *(float4*)(OUT + (size_t)(row0 + ty * 4 + i) * OC + col0 + tx * 4) = o;
    }
}

// ---------------------------------------------------------------------------
// V projection via tf32 mma.sync: OUT = tf32(X) @ tf32(Wv), result rounded to
// tf32 so the attention kernel consumes pre-rounded V.
// CTA = 64x64 tile, 8 warps (4 Mx2 N), k-chunk 16.
// ---------------------------------------------------------------------------
__global__ __launch_bounds__(256)
void vproj_kernel(const float* __restrict__ im1, const float* __restrict__ im2,
                  const float* __restrict__ Wv) {
    const float* X  = blockIdx.z ? im2 : im1;
    float*       OUT = blockIdx.z ? g_V2 : g_V1;
    int row0 = blockIdx.x * 64;
    int c0   = blockIdx.y * 64;

    __shared__ float Xs[64 * 20];
    __shared__ float Ws[16 * 72];

    int tid = threadIdx.x, w = tid >> 5, lane = tid & 31;
    int lr = lane >> 2, lc = lane & 3;
    int wy = w & 3, wx = w >> 2;

    float acc[4][4];
    #pragma unroll
    for (int j = 0; j < 4; j++)
        #pragma unroll
        for (int c = 0; c < 4; c++) acc[j][c] = 0.f;

    for (int k0 = 0; k0 < CDIM; k0 += 16) {
        __syncthreads();
        {
            int r = tid >> 2, c = (tid & 3) * 4;
            float4 v = *(const float4*)(X + (size_t)(row0 + r) * CDIM + k0 + c);
            Xs[r * 20 + c + 0] = tf32r(v.x); Xs[r * 20 + c + 1] = tf32r(v.y);
            Xs[r * 20 + c + 2] = tf32r(v.z); Xs[r * 20 + c + 3] = tf32r(v.w);
            int r2 = tid >> 4, c2 = (tid & 15) * 4;
            float4 u = *(const float4*)(Wv + (size_t)(k0 + r2) * CDIM + c0 + c2);
            Ws[r2 * 72 + c2 + 0] = tf32r(u.x); Ws[r2 * 72 + c2 + 1] = tf32r(u.y);
            Ws[r2 * 72 + c2 + 2] = tf32r(u.z); Ws[r2 * 72 + c2 + 3] = tf32r(u.w);
        }
        __syncthreads();
        #pragma unroll
        for (int kk = 0; kk < 2; kk++) {
            int kc = kk * 8;
            float a[4];
            int r = wy * 16 + lr;
            a[0] = Xs[r * 20 + kc + lc];       a[1] = Xs[(r + 8) * 20 + kc + lc];
            a[2] = Xs[r * 20 + kc + 4 + lc];   a[3] = Xs[(r + 8) * 20 + kc + 4 + lc];
            #pragma unroll
            for (int j = 0; j < 4; j++) {
                int n = wx * 32 + j * 8 + lr;
                float b0 = Ws[(kc + lc) * 72 + n];
                float b1 = Ws[(kc + 4 + lc) * 72 + n];
                mma8(acc[j], a, b0, b1);
            }
        }
    }
    #pragma unroll
    for (int j = 0; j < 4; j++) {
        int r = row0 + wy * 16 + lr;
        int c = c0 + wx * 32 + j * 8 + lc * 2;
        float2 o0 = make_float2(tf32r(acc[j][0]), tf32r(acc[j][1]));
        float2 o1 = make_float2(tf32r(acc[j][2]), tf32r(acc[j][3]));
        *(float2*)(OUT + (size_t)r * CDIM + c) = o0;
        *(float2*)(OUT + (size_t)(r + 8) * CDIM + c) = o1;
    }
}

// ---------------------------------------------------------------------------
// Fused attention with tf32 mma.sync.
//   CTA: 128 query rows x 256 channels; key tiles of 64; 256 threads (8 warps).
//   Logits L[128,64] = Q @ K^T via 3xTF32 split (near-fp32 accuracy).
//   P = exp(L) (no max subtraction; logits bounded ~|61|), rounded to tf32.
//   O += P @ V via single-pass tf32.  Denominator accumulated, divide at end.
// Warp partition (w = 0..7, wm = w&3, wn = w>>2):
//   logits: warp = rows 32*wm.., cols 32*wn..  (frags i in 0..1, j in 0..3)
//   PV:     warp = rows 32*wm.., cols 128*wn.. (frags i in 0..1, j in 0..15)
// ---------------------------------------------------------------------------
#define MT  128
#define NT  256
#define ST  64
#define QS  68
#define VSD 264

__global__ __launch_bounds__(256)
void attn_mma_kernel(const float* __restrict__ im1, const float* __restrict__ im2,
                     float* __restrict__ out) {
    const float *Q, *K, *V, *R;
    float* O;
    if (blockIdx.z == 0) { Q = g_Q2; K = g_K1; V = g_V1; R = im1; O = out; }
    else                 { Q = g_Q1; K = g_K2; V = g_V2; R = im2;
                           O = out + (size_t)NROWS * CDIM; }
    const int q0   = blockIdx.x * MT;
    const int col0 = blockIdx.y * NT;

    extern __shared__ float sm[];
    float* Qh   = sm;                  // [128][68]
    float* Ql   = Qh + MT * QS;        // [128][68]
    float* Kh   = Ql + MT * QS;        // [64][68]
    float* Kl   = Kh + ST * QS;        // [64][68]
    float* Vs   = Kl + ST * QS;        // [64][264]
    float* Ps   = Vs + ST * VSD;       // [128][68]
    float* rp   = Ps + MT * QS;        // [2][128]
    float* dden = rp + 2 * MT;         // [128]

    const int tid  = threadIdx.x;
    const int w    = tid >> 5, lane = tid & 31;
    const int lr   = lane >> 2, lc = lane & 3;
    const int wm   = w & 3, wn = w >> 2;

    // Load Q tile once, split into tf32 hi/lo.
    // 128 rows x 64 cols = 2048 float4 -> 8 iterations of 256 threads.
    #pragma unroll
    for (int t = 0; t < 8; t++) {
        int e = tid + t * 256;
        int r = e >> 4, c = (e & 15) * 4;
        float4 v = *(const float4*)(Q + (size_t)(q0 + r) * DK + c);
        float h;
        h = tf32r(v.x); Qh[r * QS + c + 0] = h; Ql[r * QS + c + 0] = tf32r(v.x - h);
        h = tf32r(v.y); Qh[r * QS + c + 1] = h; Ql[r * QS + c + 1] = tf32r(v.y - h);
        h = tf32r(v.z); Qh[r * QS + c + 2] = h; Ql[r * QS + c + 2] = tf32r(v.z - h);
        h = tf32r(v.w); Qh[r * QS + c + 3] = h; Ql[r * QS + c + 3] = tf32r(v.w - h);
    }
    if (tid < MT) dden[tid] = 0.f;

    float acc[2][16][4];
    #pragma unroll
    for (int i = 0; i < 2; i++)
        #pragma unroll
        for (int j = 0; j < 16; j++)
            #pragma unroll
            for (int c = 0; c < 4; c++) acc[i][j][c] = 0.f;

    for (int kt = 0; kt < NROWS / ST; kt++) {
        const int k0 = kt * ST;
        __syncthreads();
        // K tile (64x64), split hi/lo
        #pragma unroll
        for (int t = 0; t < 4; t++) {
            int e = tid + t * 256;
            int r = e >> 4, c = (e & 15) * 4;
            float4 v = *(const float4*)(K + (size_t)(k0 + r) * DK + c);
            float h;
            h = tf32r(v.x); Kh[r * QS + c + 0] = h; Kl[r * QS + c + 0] = tf32r(v.x - h);
            h = tf32r(v.y); Kh[r * QS + c + 1] = h; Kl[r * QS + c + 1] = tf32r(v.y - h);
            h = tf32r(v.z); Kh[r * QS + c + 2] = h; Kl[r * QS + c + 2] = tf32r(v.z - h);
            h = tf32r(v.w); Kh[r * QS + c + 3] = h; Kl[r * QS + c + 3] = tf32r(v.w - h);
        }
        // V tile (64x256), already tf32-rounded by vproj
        #pragma unroll
        for (int t = 0; t < 16; t++) {
            int e = tid + t * 256;
            int r = e >> 6, c = (e & 63) * 4;
            *(float4*)(Vs + r * VSD + c) =
                *(const float4*)(V + (size_t)(k0 + r) * CDIM + col0 + c);
        }
        __syncthreads();

        // ---- logits: L[128,64], 3xTF32 ----
        float L[2][4][4];
        #pragma unroll
        for (int i = 0; i < 2; i++)
            #pragma unroll
            for (int j = 0; j < 4; j++)
                #pragma unroll
                for (int c = 0; c < 4; c++) L[i][j][c] = 0.f;

        #pragma unroll
        for (int kk = 0; kk < 8; kk++) {
            const int kc = kk * 8;
            float ah[2][4], al[2][4];
            #pragma unroll
            for (int i = 0; i < 2; i++) {
                int r = wm * 32 + i * 16 + lr;
                ah[i][0] = Qh[r * QS + kc + lc];       ah[i][1] = Qh[(r + 8) * QS + kc + lc];
                ah[i][2] = Qh[r * QS + kc + 4 + lc];   ah[i][3] = Qh[(r + 8) * QS + kc + 4 + lc];
                al[i][0] = Ql[r * QS + kc + lc];       al[i][1] = Ql[(r + 8) * QS + kc + lc];
                al[i][2] = Ql[r * QS + kc + 4 + lc];   al[i][3] = Ql[(r + 8) * QS + kc + 4 + lc];
            }
            #pragma unroll
            for (int j = 0; j < 4; j++) {
                int n = wn * 32 + j * 8 + lr;
                float bh0 = Kh[n * QS + kc + lc], bh1 = Kh[n * QS + kc + 4 + lc];
                float bl0 = Kl[n * QS + kc + lc], bl1 = Kl[n * QS + kc + 4 + lc];
                #pragma unroll
                for (int i = 0; i < 2; i++) {
                    mma8(L[i][j], ah[i], bh0, bh1);
                    mma8(L[i][j], al[i], bh0, bh1);
                    mma8(L[i][j], ah[i], bl0, bl1);
                }
            }
        }

        // ---- exp, write P (tf32), partial row sums ----
        float rs[2][2] = {{0.f, 0.f}, {0.f, 0.f}};
        #pragma unroll
        for (int i = 0; i < 2; i++) {
            #pragma unroll
            for (int j = 0; j < 4; j++) {
                float p0 = __expf(L[i][j][0]), p1 = __expf(L[i][j][1]);
                float p2 = __expf(L[i][j][2]), p3 = __expf(L[i][j][3]);
                rs[i][0] += p0 + p1;
                rs[i][1] += p2 + p3;
                int r = wm * 32 + i * 16 + lr;
                int c = wn * 32 + j * 8 + lc * 2;
                *(float2*)(Ps + r * QS + c)       = make_float2(tf32r(p0), tf32r(p1));
                *(float2*)(Ps + (r + 8) * QS + c) = make_float2(tf32r(p2), tf32r(p3));
            }
        }
        #pragma unroll
        for (int i = 0; i < 2; i++)
            #pragma unroll
            for (int hh = 0; hh < 2; hh++) {
                float s = rs[i][hh];
                s += __shfl_xor_sync(0xffffffffu, s, 1);
                s += __shfl_xor_sync(0xffffffffu, s, 2);
                rs[i][hh] = s;
            }
        if (lc == 0) {
            #pragma unroll
            for (int i = 0; i < 2; i++) {
                rp[wn * MT + wm * 32 + i * 16 + lr]     = rs[i][0];
                rp[wn * MT + wm * 32 + i * 16 + lr + 8] = rs[i][1];
            }
        }
        __syncthreads();
        if (tid < MT) dden[tid] += rp[tid] + rp[MT + tid];

        // ---- PV: O += P @ V ----
        #pragma unroll
        for (int kk = 0; kk < 8; kk++) {
            const int kc = kk * 8;
            float a[2][4];
            #pragma unroll
            for (int i = 0; i < 2; i++) {
                int r = wm * 32 + i * 16 + lr;
                a[i][0] = Ps[r * QS + kc + lc];       a[i][1] = Ps[(r + 8) * QS + kc + lc];
                a[i][2] = Ps[r * QS + kc + 4 + lc];   a[i][3] = Ps[(r + 8) * QS + kc + 4 + lc];
            }
            #pragma unroll
            for (int j = 0; j < 16; j++) {
                int n = wn * 128 + j * 8 + lr;
                float b0 = Vs[(kc + lc) * VSD + n];
                float b1 = Vs[(kc + 4 + lc) * VSD + n];
                mma8(acc[0][j], a[0], b0, b1);
                mma8(acc[1][j], a[1], b0, b1);
            }
        }
    }
    __syncthreads();

    // ---- epilogue: normalize, residual, store ----
    #pragma unroll
    for (int i = 0; i < 2; i++) {
        int r = wm * 32 + i * 16 + lr;
        float inv0 = 1.f / dden[r];
        float inv1 = 1.f / dden[r + 8];
        size_t g0 = (size_t)(q0 + r) * CDIM;
        size_t g1 = (size_t)(q0 + r + 8) * CDIM;
        #pragma unroll
        for (int j = 0; j < 16; j++) {
            int c = col0 + wn * 128 + j * 8 + lc * 2;
            float2 r0 = *(const float2*)(R + g0 + c);
            float2 r1 = *(const float2*)(R + g1 + c);
            float2 o0 = make_float2(fmaf(acc[i][j][0], inv0, r0.x),
                                    fmaf(acc[i][j][1], inv0, r0.y));
            float2 o1 = make_float2(fmaf(acc[i][j][2], inv1, r1.x),
                                    fmaf(acc[i][j][3], inv1, r1.y));
            *(float2*)(O + g0 + c) = o0;
            *(float2*)(O + g1 + c) = o1;
        }
    }
}

// ---------------------------------------------------------------------------
extern "C" void kernel_launch(void* const* d_in, const int* in_sizes, int n_in,
                              void* d_out, int out_size) {
    const float* im1 = (const float*)d_in[0];
    const float* im2 = (const float*)d_in[1];
    const float* Wq  = (const float*)d_in[2];
    const float* Wk  = (const float*)d_in[3];
    const float* Wv  = (const float*)d_in[4];
    float* out = (float*)d_out;

    float *Q1, *K1, *Q2, *K2;
    cudaGetSymbolAddress((void**)&Q1, g_Q1);
    cudaGetSymbolAddress((void**)&K1, g_K1);
    cudaGetSymbolAddress((void**)&Q2, g_Q2);
    cudaGetSymbolAddress((void**)&K2, g_K2);

    dim3 gq(NROWS / 64, 1);
    proj_kernel<<<gq, 256>>>(im1, Wq, Q1, DK);
    proj_kernel<<<gq, 256>>>(im1, Wk, K1, DK);
    proj_kernel<<<gq, 256>>>(im2, Wq, Q2, DK);
    proj_kernel<<<gq, 256>>>(im2, Wk, K2, DK);

    vproj_kernel<<<dim3(NROWS / 64, CDIM / 64, 2), 256>>>(im1, im2, Wv);

    int smem_bytes = (2 * MT * QS + 2 * ST * QS + ST * VSD + MT * QS + 3 * MT)
                     * (int)sizeof(float);
    cudaFuncSetAttribute(attn_mma_kernel,
                         cudaFuncAttributeMaxDynamicSharedMemorySize, smem_bytes);
    attn_mma_kernel<<<dim3(NROWS / MT, CDIM / NT, 2), 256, smem_bytes>>>(im1, im2, out);
}

// round 7
// speedup vs baseline: 5.4309x; 1.7516x over previous
#include <cuda_runtime.h>
#include <cuda_fp16.h>
#include <math.h>

#define NROWS 8192
#define CDIM  512
#define DK    64

// Scratch (static __device__ globals — allocation-free per harness rules)
__device__ float  g_Q1[NROWS * DK];
__device__ float  g_K1[NROWS * DK];
__device__ float  g_Q2[NROWS * DK];
__device__ float  g_K2[NROWS * DK];
// V stored as fp16, pair-interleaved: half2 at [k>>1][n] holds (V[k][n], V[k+1][n])
__device__ __half g_V1[NROWS * CDIM];
__device__ __half g_V2[NROWS * CDIM];

// ---------------------------------------------------------------------------
// helpers
// ---------------------------------------------------------------------------
__device__ __forceinline__ void mma16(float c[4], const unsigned a[4],
                                      unsigned b0, unsigned b1) {
    asm volatile(
        "mma.sync.aligned.m16n8k16.row.col.f32.f16.f16.f32 "
        "{%0,%1,%2,%3},{%4,%5,%6,%7},{%8,%9},{%0,%1,%2,%3};"
        : "+f"(c[0]), "+f"(c[1]), "+f"(c[2]), "+f"(c[3])
        : "r"(a[0]), "r"(a[1]), "r"(a[2]), "r"(a[3]), "r"(b0), "r"(b1));
}

__device__ __forceinline__ void splith(float v, __half& h, __half& l) {
    h = __float2half_rn(v);
    l = __float2half_rn(v - __half2float(h));
}

__device__ __forceinline__ unsigned h2u(__half2 h) {
    return *reinterpret_cast<unsigned*>(&h);
}

// ---------------------------------------------------------------------------
// Q/K projections (FFMA fp32, logits need full-precision Q,K).
// All four (im x {Wq,Wk}) in one launch: blockIdx.y selects.
// ---------------------------------------------------------------------------
__global__ __launch_bounds__(256)
void qkproj_kernel(const float* __restrict__ im1, const float* __restrict__ im2,
                   const float* __restrict__ Wq, const float* __restrict__ Wk) {
    const int sel = blockIdx.y;
    const float* X = (sel & 2) ? im2 : im1;
    const float* W = (sel & 1) ? Wk : Wq;
    float* OUT;
    switch (sel) {
        case 0: OUT = g_Q1; break;
        case 1: OUT = g_K1; break;
        case 2: OUT = g_Q2; break;
        default: OUT = g_K2; break;
    }
    __shared__ float Xs[64][17];
    __shared__ float Ws[16][64];
    int tid  = threadIdx.x;
    int row0 = blockIdx.x * 64;

    int lr = tid >> 2, lc = (tid & 3) * 4;
    int wr = tid >> 4, wc = (tid & 15) * 4;
    int ty = tid >> 4, tx = tid & 15;

    float acc[4][4];
    #pragma unroll
    for (int i = 0; i < 4; i++)
        #pragma unroll
        for (int j = 0; j < 4; j++) acc[i][j] = 0.f;

    for (int k0 = 0; k0 < CDIM; k0 += 16) {
        __syncthreads();
        float4 xv = *(const float4*)(X + (size_t)(row0 + lr) * CDIM + k0 + lc);
        Xs[lr][lc + 0] = xv.x; Xs[lr][lc + 1] = xv.y;
        Xs[lr][lc + 2] = xv.z; Xs[lr][lc + 3] = xv.w;
        *(float4*)(&Ws[wr][wc]) =
            *(const float4*)(W + (size_t)(k0 + wr) * DK + wc);
        __syncthreads();
        #pragma unroll
        for (int kk = 0; kk < 16; kk++) {
            float a[4], b[4];
            #pragma unroll
            for (int i = 0; i < 4; i++) a[i] = Xs[ty * 4 + i][kk];
            #pragma unroll
            for (int j = 0; j < 4; j++) b[j] = Ws[kk][tx * 4 + j];
            #pragma unroll
            for (int i = 0; i < 4; i++)
                #pragma unroll
                for (int j = 0; j < 4; j++)
                    acc[i][j] = fmaf(a[i], b[j], acc[i][j]);
        }
    }
    #pragma unroll
    for (int i = 0; i < 4; i++) {
        float4 o = make_float4(acc[i][0], acc[i][1], acc[i][2], acc[i][3]);
        *(float4*)(OUT + (size_t)(row0 + ty * 4 + i) * DK + tx * 4) = o;
    }
}

// ---------------------------------------------------------------------------
// V projection with fp16 m16n8k16. Output fp16, pair-interleaved (k,k+1) half2.
// CTA = 64 rows x 64 cols, 8 warps (wy 0..3 = 16-row bands, wx 0..1 = 32-col).
// ---------------------------------------------------------------------------
__global__ __launch_bounds__(256)
void vproj_kernel(const float* __restrict__ im1, const float* __restrict__ im2,
                  const float* __restrict__ Wv) {
    const float* X = blockIdx.z ? im2 : im1;
    __half* OUT    = blockIdx.z ? g_V2 : g_V1;
    const int row0 = blockIdx.x * 64;
    const int c0   = blockIdx.y * 64;

    __shared__ __half2 Xs2[64 * 12];   // [row][k2], stride 12
    __shared__ __half2 Ws2[8 * 72];    // [k2][n],  stride 72
    const unsigned* Xs2u = (const unsigned*)Xs2;
    const unsigned* Ws2u = (const unsigned*)Ws2;

    int tid = threadIdx.x, w = tid >> 5, lane = tid & 31;
    int lr = lane >> 2, lc = lane & 3;
    int wy = w & 3, wx = w >> 2;

    float acc[4][4];
    #pragma unroll
    for (int j = 0; j < 4; j++)
        #pragma unroll
        for (int c = 0; c < 4; c++) acc[j][c] = 0.f;

    for (int k0 = 0; k0 < CDIM; k0 += 16) {
        __syncthreads();
        {
            // X chunk: 64 rows x 16 k
            int r = tid >> 2, c = (tid & 3) * 4;
            float4 v = *(const float4*)(X + (size_t)(row0 + r) * CDIM + k0 + c);
            Xs2[r * 12 + (tid & 3) * 2 + 0] =
                __halves2half2(__float2half_rn(v.x), __float2half_rn(v.y));
            Xs2[r * 12 + (tid & 3) * 2 + 1] =
                __halves2half2(__float2half_rn(v.z), __float2half_rn(v.w));
            // W chunk: 16 k x 64 n, packed as (k,k+1) pairs
            int k2 = tid >> 5, n = (tid & 31) * 2;
            float2 wa = *(const float2*)(Wv + (size_t)(k0 + 2 * k2) * CDIM + c0 + n);
            float2 wb = *(const float2*)(Wv + (size_t)(k0 + 2 * k2 + 1) * CDIM + c0 + n);
            Ws2[k2 * 72 + n + 0] =
                __halves2half2(__float2half_rn(wa.x), __float2half_rn(wb.x));
            Ws2[k2 * 72 + n + 1] =
                __halves2half2(__float2half_rn(wa.y), __float2half_rn(wb.y));
        }
        __syncthreads();
        {
            int r = wy * 16 + lr;
            unsigned a[4];
            a[0] = Xs2u[r * 12 + lc];
            a[1] = Xs2u[(r + 8) * 12 + lc];
            a[2] = Xs2u[r * 12 + 4 + lc];
            a[3] = Xs2u[(r + 8) * 12 + 4 + lc];
            #pragma unroll
            for (int j = 0; j < 4; j++) {
                int n = wx * 32 + j * 8 + lr;
                unsigned b0 = Ws2u[lc * 72 + n];
                unsigned b1 = Ws2u[(lc + 4) * 72 + n];
                mma16(acc[j], a, b0, b1);
            }
        }
    }

    // Epilogue: pair rows (k, k+1) across lr-adjacent threads, store half2.
    __half2* OUT2 = (__half2*)OUT;
    #pragma unroll
    for (int j = 0; j < 4; j++) {
        int n = c0 + wx * 32 + j * 8 + lc * 2;   // even channel index
        float p0 = __shfl_xor_sync(0xffffffffu, acc[j][0], 4);
        float p1 = __shfl_xor_sync(0xffffffffu, acc[j][1], 4);
        float p2 = __shfl_xor_sync(0xffffffffu, acc[j][2], 4);
        float p3 = __shfl_xor_sync(0xffffffffu, acc[j][3], 4);
        int base = row0 + wy * 16 + lr;
        if (!(lr & 1)) {
            // rows (base, base+1): own c0/c1 + partner p0/p1
            int k2 = base >> 1;
            __half2 h0 = __halves2half2(__float2half_rn(acc[j][0]), __float2half_rn(p0));
            __half2 h1 = __halves2half2(__float2half_rn(acc[j][1]), __float2half_rn(p1));
            uint2 u; u.x = h2u(h0); u.y = h2u(h1);
            *(uint2*)(OUT2 + (size_t)k2 * CDIM + n) = u;
        } else {
            // rows (base+7, base+8): partner p2/p3 (even row) + own c2/c3
            int k2 = (base + 7) >> 1;
            __half2 h0 = __halves2half2(__float2half_rn(p2), __float2half_rn(acc[j][2]));
            __half2 h1 = __halves2half2(__float2half_rn(p3), __float2half_rn(acc[j][3]));
            uint2 u; u.x = h2u(h0); u.y = h2u(h1);
            *(uint2*)(OUT2 + (size_t)k2 * CDIM + n) = u;
        }
    }
}

// ---------------------------------------------------------------------------
// Fused flash attention, fp16 m16n8k16.
//   CTA: 128 q-rows x 256 channels, key tiles of 64, 256 threads (8 warps).
//   Logits: 2-term fp16 hi/lo split of Q,K (hh + lh + hl) -> ~22-bit accuracy.
//   Online row-max (flash rescaling) so P=exp(L-m) fits fp16.
//   PV: P fp16 x V fp16, fp32 accumulate.
// Warp partition (wm = w&3 rows, wn = w>>2):
//   logits: rows 32*wm, cols 32*wn (j=0..3);  PV: rows 32*wm, cols 128*wn (j=0..15)
// ---------------------------------------------------------------------------
#define MT   128
#define NT   256
#define ST   64
#define QS2  36    // half2 stride for Q/K/P tiles
#define VS2D 264   // half2 stride for V tile rows (k2-major)

__global__ __launch_bounds__(256, 1)
void attn_mma_kernel(const float* __restrict__ im1, const float* __restrict__ im2,
                     float* __restrict__ out) {
    const float *Q, *K, *R;
    const __half* Vh;
    float* O;
    if (blockIdx.z == 0) { Q = g_Q2; K = g_K1; Vh = g_V1; R = im1; O = out; }
    else                 { Q = g_Q1; K = g_K2; Vh = g_V2; R = im2;
                           O = out + (size_t)NROWS * CDIM; }
    const int q0   = blockIdx.x * MT;
    const int col0 = blockIdx.y * NT;

    extern __shared__ char smraw[];
    __half2* Qh2 = (__half2*)smraw;          // [128][36]
    __half2* Ql2 = Qh2 + MT * QS2;           // [128][36]
    __half2* Kh2 = Ql2 + MT * QS2;           // [64][36]
    __half2* Kl2 = Kh2 + ST * QS2;           // [64][36]
    __half2* Vs2 = Kl2 + ST * QS2;           // [32][264]
    __half2* Ps2 = Vs2 + (ST / 2) * VS2D;    // [128][36]
    float* rp   = (float*)(Ps2 + MT * QS2);  // [2][128]
    float* dden = rp + 2 * MT;               // [128]
    float* mst  = dden + MT;                 // [128] running max
    float* fb   = mst + MT;                  // [128] rescale factor
    float* mnb  = fb + MT;                   // [128] new max broadcast

    const unsigned* Qh2u = (const unsigned*)Qh2;
    const unsigned* Ql2u = (const unsigned*)Ql2;
    const unsigned* Kh2u = (const unsigned*)Kh2;
    const unsigned* Kl2u = (const unsigned*)Kl2;
    const unsigned* Vs2u = (const unsigned*)Vs2;
    const unsigned* Ps2u = (const unsigned*)Ps2;

    const int tid  = threadIdx.x;
    const int w    = tid >> 5, lane = tid & 31;
    const int lr   = lane >> 2, lc = lane & 3;
    const int wm   = w & 3, wn = w >> 2;

    // Load Q tile once (128x64 fp32 = 2048 float4 -> 8 iters), split hi/lo fp16.
    #pragma unroll
    for (int t = 0; t < 8; t++) {
        int e = tid + t * 256;
        int r = e >> 4, c4 = (e & 15) * 4, c2 = (e & 15) * 2;
        float4 v = *(const float4*)(Q + (size_t)(q0 + r) * DK + c4);
        __half h0, l0, h1, l1, h2, l2, h3, l3;
        splith(v.x, h0, l0); splith(v.y, h1, l1);
        splith(v.z, h2, l2); splith(v.w, h3, l3);
        Qh2[r * QS2 + c2 + 0] = __halves2half2(h0, h1);
        Qh2[r * QS2 + c2 + 1] = __halves2half2(h2, h3);
        Ql2[r * QS2 + c2 + 0] = __halves2half2(l0, l1);
        Ql2[r * QS2 + c2 + 1] = __halves2half2(l2, l3);
    }
    if (tid < MT) { dden[tid] = 0.f; mst[tid] = -INFINITY; }

    float acc[2][16][4];
    #pragma unroll
    for (int i = 0; i < 2; i++)
        #pragma unroll
        for (int j = 0; j < 16; j++)
            #pragma unroll
            for (int c = 0; c < 4; c++) acc[i][j][c] = 0.f;

    const __half2* Vg2 = (const __half2*)Vh;

    for (int kt = 0; kt < NROWS / ST; kt++) {
        const int k0  = kt * ST;
        const int k02 = k0 >> 1;
        __syncthreads();   // protect smem reuse vs previous tile's PV reads

        // K tile (64x64 fp32 = 1024 float4 -> 4 iters), hi/lo split; [key][k2]
        #pragma unroll
        for (int t = 0; t < 4; t++) {
            int e = tid + t * 256;
            int r = e >> 4, c4 = (e & 15) * 4, c2 = (e & 15) * 2;
            float4 v = *(const float4*)(K + (size_t)(k0 + r) * DK + c4);
            __half h0, l0, h1, l1, h2, l2, h3, l3;
            splith(v.x, h0, l0); splith(v.y, h1, l1);
            splith(v.z, h2, l2); splith(v.w, h3, l3);
            Kh2[r * QS2 + c2 + 0] = __halves2half2(h0, h1);
            Kh2[r * QS2 + c2 + 1] = __halves2half2(h2, h3);
            Kl2[r * QS2 + c2 + 0] = __halves2half2(l0, l1);
            Kl2[r * QS2 + c2 + 1] = __halves2half2(l2, l3);
        }
        // V tile: 32 k2-rows x 256 half2 -> 2048 uint4 -> 8 iters
        #pragma unroll
        for (int t = 0; t < 8; t++) {
            int e = tid + t * 256;
            int r = e >> 6, cu = (e & 63) * 4;
            uint4 v = *(const uint4*)(Vg2 + (size_t)(k02 + r) * CDIM + col0 + cu);
            *(uint4*)(Vs2 + r * VS2D + cu) = v;
        }
        __syncthreads();

        // ---- logits (fp16 3-product split) ----
        float L[2][4][4];
        #pragma unroll
        for (int i = 0; i < 2; i++)
            #pragma unroll
            for (int j = 0; j < 4; j++)
                #pragma unroll
                for (int c = 0; c < 4; c++) L[i][j][c] = 0.f;

        #pragma unroll
        for (int kk = 0; kk < 4; kk++) {
            const int kc2 = kk * 8;
            unsigned ah[2][4], al[2][4];
            #pragma unroll
            for (int i = 0; i < 2; i++) {
                int r = wm * 32 + i * 16 + lr;
                ah[i][0] = Qh2u[r * QS2 + kc2 + lc];
                ah[i][1] = Qh2u[(r + 8) * QS2 + kc2 + lc];
                ah[i][2] = Qh2u[r * QS2 + kc2 + 4 + lc];
                ah[i][3] = Qh2u[(r + 8) * QS2 + kc2 + 4 + lc];
                al[i][0] = Ql2u[r * QS2 + kc2 + lc];
                al[i][1] = Ql2u[(r + 8) * QS2 + kc2 + lc];
                al[i][2] = Ql2u[r * QS2 + kc2 + 4 + lc];
                al[i][3] = Ql2u[(r + 8) * QS2 + kc2 + 4 + lc];
            }
            #pragma unroll
            for (int j = 0; j < 4; j++) {
                int n = wn * 32 + j * 8 + lr;
                unsigned bh0 = Kh2u[n * QS2 + kc2 + lc];
                unsigned bh1 = Kh2u[n * QS2 + kc2 + 4 + lc];
                unsigned bl0 = Kl2u[n * QS2 + kc2 + lc];
                unsigned bl1 = Kl2u[n * QS2 + kc2 + 4 + lc];
                #pragma unroll
                for (int i = 0; i < 2; i++) {
                    mma16(L[i][j], ah[i], bh0, bh1);
                    mma16(L[i][j], al[i], bh0, bh1);
                    mma16(L[i][j], ah[i], bl0, bl1);
                }
            }
        }

        // ---- tile row max ----
        #pragma unroll
        for (int i = 0; i < 2; i++) {
            float m0 = -INFINITY, m1 = -INFINITY;
            #pragma unroll
            for (int j = 0; j < 4; j++) {
                m0 = fmaxf(m0, fmaxf(L[i][j][0], L[i][j][1]));
                m1 = fmaxf(m1, fmaxf(L[i][j][2], L[i][j][3]));
            }
            m0 = fmaxf(m0, __shfl_xor_sync(0xffffffffu, m0, 1));
            m0 = fmaxf(m0, __shfl_xor_sync(0xffffffffu, m0, 2));
            m1 = fmaxf(m1, __shfl_xor_sync(0xffffffffu, m1, 1));
            m1 = fmaxf(m1, __shfl_xor_sync(0xffffffffu, m1, 2));
            if (lc == 0) {
                rp[wn * MT + wm * 32 + i * 16 + lr]     = m0;
                rp[wn * MT + wm * 32 + i * 16 + lr + 8] = m1;
            }
        }
        __syncthreads();
        if (tid < MT) {
            float mt2 = fmaxf(rp[tid], rp[MT + tid]);
            float mo  = mst[tid];
            float mn  = fmaxf(mo, mt2);
            mst[tid] = mn;
            mnb[tid] = mn;
            fb[tid]  = __expf(mo - mn);   // 0 on first tile (mo = -inf)
        }
        __syncthreads();

        // ---- exp, pack P, partial sums, rescale acc ----
        float rs[2][2] = {{0.f, 0.f}, {0.f, 0.f}};
        #pragma unroll
        for (int i = 0; i < 2; i++) {
            int r = wm * 32 + i * 16 + lr;
            float mn0 = mnb[r], mn1 = mnb[r + 8];
            #pragma unroll
            for (int j = 0; j < 4; j++) {
                float p0 = __expf(L[i][j][0] - mn0);
                float p1 = __expf(L[i][j][1] - mn0);
                float p2 = __expf(L[i][j][2] - mn1);
                float p3 = __expf(L[i][j][3] - mn1);
                rs[i][0] += p0 + p1;
                rs[i][1] += p2 + p3;
                int c2 = wn * 16 + j * 4 + lc;
                Ps2[r * QS2 + c2]       = __floats2half2_rn(p0, p1);
                Ps2[(r + 8) * QS2 + c2] = __floats2half2_rn(p2, p3);
            }
            // rescale accumulators for these rows
            float f0 = fb[r], f1 = fb[r + 8];
            #pragma unroll
            for (int j = 0; j < 16; j++) {
                acc[i][j][0] *= f0; acc[i][j][1] *= f0;
                acc[i][j][2] *= f1; acc[i][j][3] *= f1;
            }
        }
        #pragma unroll
        for (int i = 0; i < 2; i++)
            #pragma unroll
            for (int hh = 0; hh < 2; hh++) {
                float s = rs[i][hh];
                s += __shfl_xor_sync(0xffffffffu, s, 1);
                s += __shfl_xor_sync(0xffffffffu, s, 2);
                rs[i][hh] = s;
            }
        if (lc == 0) {
            #pragma unroll
            for (int i = 0; i < 2; i++) {
                rp[wn * MT + wm * 32 + i * 16 + lr]     = rs[i][0];
                rp[wn * MT + wm * 32 + i * 16 + lr + 8] = rs[i][1];
            }
        }
        __syncthreads();
        if (tid < MT) dden[tid] = dden[tid] * fb[tid] + rp[tid] + rp[MT + tid];

        // ---- PV: O += P @ V ----
        #pragma unroll
        for (int kk = 0; kk < 4; kk++) {
            const int kc2 = kk * 8;
            unsigned a[2][4];
            #pragma unroll
            for (int i = 0; i < 2; i++) {
                int r = wm * 32 + i * 16 + lr;
                a[i][0] = Ps2u[r * QS2 + kc2 + lc];
                a[i][1] = Ps2u[(r + 8) * QS2 + kc2 + lc];
                a[i][2] = Ps2u[r * QS2 + kc2 + 4 + lc];
                a[i][3] = Ps2u[(r + 8) * QS2 + kc2 + 4 + lc];
            }
            #pragma unroll
            for (int j = 0; j < 16; j++) {
                int n = wn * 128 + j * 8 + lr;
                unsigned b0 = Vs2u[(kc2 + lc) * VS2D + n];
                unsigned b1 = Vs2u[(kc2 + lc + 4) * VS2D + n];
                mma16(acc[0][j], a[0], b0, b1);
                mma16(acc[1][j], a[1], b0, b1);
            }
        }
    }
    __syncthreads();

    // ---- epilogue: normalize, residual, store ----
    #pragma unroll
    for (int i = 0; i < 2; i++) {
        int r = wm * 32 + i * 16 + lr;
        float inv0 = 1.f / dden[r];
        float inv1 = 1.f / dden[r + 8];
        size_t g0 = (size_t)(q0 + r) * CDIM;
        size_t g1 = (size_t)(q0 + r + 8) * CDIM;
        #pragma unroll
        for (int j = 0; j < 16; j++) {
            int c = col0 + wn * 128 + j * 8 + lc * 2;
            float2 r0 = *(const float2*)(R + g0 + c);
            float2 r1 = *(const float2*)(R + g1 + c);
            float2 o0 = make_float2(fmaf(acc[i][j][0], inv0, r0.x),
                                    fmaf(acc[i][j][1], inv0, r0.y));
            float2 o1 = make_float2(fmaf(acc[i][j][2], inv1, r1.x),
                                    fmaf(acc[i][j][3], inv1, r1.y));
            *(float2*)(O + g0 + c) = o0;
            *(float2*)(O + g1 + c) = o1;
        }
    }
}

// ---------------------------------------------------------------------------
extern "C" void kernel_launch(void* const* d_in, const int* in_sizes, int n_in,
                              void* d_out, int out_size) {
    const float* im1 = (const float*)d_in[0];
    const float* im2 = (const float*)d_in[1];
    const float* Wq  = (const float*)d_in[2];
    const float* Wk  = (const float*)d_in[3];
    const float* Wv  = (const float*)d_in[4];
    float* out = (float*)d_out;

    qkproj_kernel<<<dim3(NROWS / 64, 4), 256>>>(im1, im2, Wq, Wk);
    vproj_kernel<<<dim3(NROWS / 64, CDIM / 64, 2), 256>>>(im1, im2, Wv);

    int smem_bytes = (2 * MT * QS2 + 2 * ST * QS2 + (ST / 2) * VS2D + MT * QS2) * 4
                     + (2 * MT + 4 * MT) * (int)sizeof(float);
    cudaFuncSetAttribute(attn_mma_kernel,
                         cudaFuncAttributeMaxDynamicSharedMemorySize, smem_bytes);
    attn_mma_kernel<<<dim3(NROWS / MT, CDIM / NT, 2), 256, smem_bytes>>>(im1, im2, out);
}